// round 14
// baseline (speedup 1.0000x reference)
#include <cuda_runtime.h>
#include <cuda_fp16.h>
#include <cstdint>

#define D       64
#define HW      4096
#define KCODES  1024
#define NTOK    65536

// codebook pre-scale 2^10 (exact); screening scale-back 2^-9 = 2*EINV (exact)
#define ESCALE     1024.0f
#define NEG2EINV  (-0.001953125f)

// ---------------- device scratch (no allocation allowed) -------------------
__device__ uint4 g_Eh4[8192];     // 128KB: hi-plane B fragments, all 1024 codes
__device__ float g_sse[KCODES];
__device__ int   g_nfb;           // fallback count
__device__ int   g_fb[NTOK];      // fallback token list

__device__ __forceinline__ uint32_t packh(float x0, float x1) {
    uint32_t r;
    asm("cvt.rn.f16x2.f32 %0, %1, %2;" : "=r"(r) : "f"(x1), "f"(x0));
    return r;
}

// C += A(f16 16x16) * B(f16 16x8), fp32 accumulate.
__device__ __forceinline__ void mma_f16(float c[4], const uint32_t* a,
                                        uint32_t b0, uint32_t b1) {
    asm("mma.sync.aligned.m16n8k16.row.col.f32.f16.f16.f32 "
        "{%0,%1,%2,%3}, {%4,%5,%6,%7}, {%8,%9}, {%0,%1,%2,%3};"
        : "+f"(c[0]), "+f"(c[1]), "+f"(c[2]), "+f"(c[3])
        : "r"(a[0]), "r"(a[1]), "r"(a[2]), "r"(a[3]), "r"(b0), "r"(b1));
}

// ---------------- prep: codebook -> f16 hi B-fragments (scaled) + sse ------
__global__ void vq_prep(const float* __restrict__ cb) {
    int id = blockIdx.x * blockDim.x + threadIdx.x;   // 65536 = 1024*64
    if (id == 0) g_nfb = 0;
    int n = id >> 6, k = id & 63;
    __half hi = __float2half(cb[id] * ESCALE);
    int ntile = n >> 3, nrow = n & 7;
    int kstep = k >> 4, kin = k & 15;
    int j    = kin >> 3;
    int cb4  = (kin & 7) >> 1;
    int elem = k & 1;
    int idx2 = (ntile * 4 + kstep) * 32 + nrow * 4 + cb4;   // uint2 slots
    ((__half*)g_Eh4)[idx2 * 4 + j * 2 + elem] = hi;
    if (k == 0) {   // sequential row sum, unscaled
        const float* r = cb + n * D;
        float s = 0.0f;
        for (int d0 = 0; d0 < D; ++d0) s += r[d0] * r[d0];
        g_sse[n] = s;
    }
}

#define SMEM_REQ (131072 + 4096)
#define THREADS  512

// top-3 insert, ascending-k stream (strict < keeps first index naturally)
#define UPD3(h, d, k)                                                        \
    if ((d) < bd3[h]) {                                                      \
        if ((d) < bd1[h]) {                                                  \
            bd3[h] = bd2[h]; bd2[h] = bd1[h]; bi2[h] = bi1[h];               \
            bd1[h] = (d);    bi1[h] = (k);                                   \
        } else if ((d) < bd2[h]) {                                           \
            bd3[h] = bd2[h]; bd2[h] = (d);   bi2[h] = (k);                   \
        } else bd3[h] = (d);                                                 \
    }

// lex insert (used in cross-lane merge, partner may hold lower equal-dist idx)
#define INS_LEX(h, d, k)                                                     \
    {                                                                        \
        bool l1 = ((d) < bd1[h]) || ((d) == bd1[h] && (k) < bi1[h]);         \
        bool l2 = ((d) < bd2[h]) || ((d) == bd2[h] && (k) < bi2[h]);         \
        if (l1)      { bd3[h]=bd2[h]; bd2[h]=bd1[h]; bi2[h]=bi1[h];          \
                       bd1[h]=(d);    bi1[h]=(k); }                          \
        else if (l2) { bd3[h]=bd2[h]; bd2[h]=(d);    bi2[h]=(k); }           \
        else if ((d) < bd3[h]) bd3[h] = (d);                                 \
    }

// ---------------- main: hi-plane screening + tiered exact resolve ----------
__global__ void __launch_bounds__(THREADS, 1)
vq_main(const float* __restrict__ input, const float* __restrict__ cb,
        float* __restrict__ out) {
    extern __shared__ char smraw[];
    uint2* sB2  = (uint2*)smraw;                 // 16384 uint2 = 128KB
    float* sSse = (float*)(smraw + 131072);      // 1024 floats

    const int tid  = threadIdx.x;
    const int w    = tid >> 5;
    const int lane = tid & 31;
    const int grp  = lane >> 2;
    const int cb4  = lane & 3;

    // stage ALL 1024 codes' hi fragments + sse once
    {
        uint4* d4 = (uint4*)smraw;
        #pragma unroll
        for (int i = 0; i < 16; ++i)
            d4[tid + i * THREADS] = g_Eh4[tid + i * THREADS];
        #pragma unroll
        for (int i = 0; i < 2; ++i)
            sSse[tid + i * THREADS] = g_sse[tid + i * THREADS];
    }
    __syncthreads();

    #pragma unroll 1
    for (int p = 0; p < 2; ++p) {
        const int base = blockIdx.x * 512 + p * 256 + w * 16;

        // ---- A hi fragment: 16 tokens ----
        uint32_t Ahi[16];
        float ssx0, ssx1;
        {
            const int row0 = base + grp;
            const int b    = row0 >> 12;
            const int hw   = row0 & (HW - 1);
            const float* p0 = input + (size_t)b * D * HW + hw;
            const float* p1 = p0 + 8;
            float s0 = 0.0f, s1 = 0.0f;
            #pragma unroll
            for (int ks = 0; ks < 4; ++ks) {
                const int k0 = ks * 16 + 2 * cb4;
                float xa, xb;
                xa = p0[(size_t)k0 * HW];        xb = p0[(size_t)(k0 + 1) * HW];
                s0 = fmaf(xa, xa, s0);           s0 = fmaf(xb, xb, s0);
                Ahi[ks * 4 + 0] = packh(xa, xb);
                xa = p1[(size_t)k0 * HW];        xb = p1[(size_t)(k0 + 1) * HW];
                s1 = fmaf(xa, xa, s1);           s1 = fmaf(xb, xb, s1);
                Ahi[ks * 4 + 1] = packh(xa, xb);
                xa = p0[(size_t)(k0 + 8) * HW];  xb = p0[(size_t)(k0 + 9) * HW];
                s0 = fmaf(xa, xa, s0);           s0 = fmaf(xb, xb, s0);
                Ahi[ks * 4 + 2] = packh(xa, xb);
                xa = p1[(size_t)(k0 + 8) * HW];  xb = p1[(size_t)(k0 + 9) * HW];
                s1 = fmaf(xa, xa, s1);           s1 = fmaf(xb, xb, s1);
                Ahi[ks * 4 + 3] = packh(xa, xb);
            }
            s0 += __shfl_xor_sync(0xffffffffu, s0, 1);
            s0 += __shfl_xor_sync(0xffffffffu, s0, 2);
            s1 += __shfl_xor_sync(0xffffffffu, s1, 1);
            s1 += __shfl_xor_sync(0xffffffffu, s1, 2);
            ssx0 = s0;
            ssx1 = s1;
        }

        float bd1[2] = {3.4e38f, 3.4e38f}, bd2[2] = {3.4e38f, 3.4e38f},
              bd3[2] = {3.4e38f, 3.4e38f};
        int   bi1[2] = {0, 0}, bi2[2] = {0, 0};

        // ---- screening: hi*hi only, all 1024 codes ----
        #pragma unroll 2
        for (int nt = 0; nt < 128; ++nt) {
            float C[4] = {0.0f, 0.0f, 0.0f, 0.0f};
            #pragma unroll
            for (int ks = 0; ks < 4; ++ks) {
                uint2 B = sB2[(nt * 4 + ks) * 32 + lane];
                mma_f16(C, &Ahi[ks * 4], B.x, B.y);
            }
            const int kg = nt * 8 + 2 * cb4;
            float2 ss = *(const float2*)&sSse[kg];
            float d00 = fmaf(C[0], NEG2EINV, ssx0 + ss.x);
            float d01 = fmaf(C[1], NEG2EINV, ssx0 + ss.y);
            float d10 = fmaf(C[2], NEG2EINV, ssx1 + ss.x);
            float d11 = fmaf(C[3], NEG2EINV, ssx1 + ss.y);
            UPD3(0, d00, kg); UPD3(0, d01, kg + 1);
            UPD3(1, d10, kg); UPD3(1, d11, kg + 1);
        }

        // ---- merge top-3 across the 4 cb4 lanes (lex on d1/d2) ----
        #pragma unroll
        for (int off = 1; off <= 2; off <<= 1) {
            #pragma unroll
            for (int h = 0; h < 2; ++h) {
                float od1 = __shfl_xor_sync(0xffffffffu, bd1[h], off);
                int   oi1 = __shfl_xor_sync(0xffffffffu, bi1[h], off);
                float od2 = __shfl_xor_sync(0xffffffffu, bd2[h], off);
                int   oi2 = __shfl_xor_sync(0xffffffffu, bi2[h], off);
                float od3 = __shfl_xor_sync(0xffffffffu, bd3[h], off);
                INS_LEX(h, od1, oi1);
                INS_LEX(h, od2, oi2);
                if (od3 < bd3[h]) bd3[h] = od3;
            }
        }

        // ---- tiered resolution + output (lanes cb4 0/1 own token h=cb4) ----
        if (cb4 < 2) {
            const int h    = cb4;
            const int row  = base + grp + h * 8;
            const int b    = row >> 12;
            const int hw   = row & (HW - 1);
            const float ssx = h ? ssx1 : ssx0;
            const float T   = fmaf(sqrtf(ssx), 3.2e-5f, 3.0e-5f);
            int win = bi1[h];
            if (bd2[h] - bd1[h] < T) {
                if (bd3[h] - bd1[h] >= T) {
                    // tier-2: exact fp32 refine of {i1, i2}
                    const float* xr = input + (size_t)b * D * HW + hw;
                    const float* e1 = cb + bi1[h] * D;
                    const float* e2 = cb + bi2[h] * D;
                    float dot1 = 0.0f, dot2 = 0.0f;
                    #pragma unroll 8
                    for (int k = 0; k < D; ++k) {
                        float xv = xr[(size_t)k * HW];
                        dot1 = fmaf(xv, __ldg(e1 + k), dot1);
                        dot2 = fmaf(xv, __ldg(e2 + k), dot2);
                    }
                    float r1 = (ssx + sSse[bi1[h]]) - 2.0f * dot1;
                    float r2 = (ssx + sSse[bi2[h]]) - 2.0f * dot2;
                    if (r2 < r1 || (r2 == r1 && bi2[h] < bi1[h])) win = bi2[h];
                } else {
                    // tier-3: full exact scan later (provisional write now)
                    int slot = atomicAdd(&g_nfb, 1);
                    g_fb[slot] = row;
                }
            }
            const float4* e  = (const float4*)cb + win * (D / 4);
            float*        op = out + (size_t)b * D * HW + hw;
            #pragma unroll
            for (int j = 0; j < D / 4; ++j) {
                float4 v = __ldg(e + j);
                op[(size_t)(4 * j + 0) * HW] = v.x;
                op[(size_t)(4 * j + 1) * HW] = v.y;
                op[(size_t)(4 * j + 2) * HW] = v.z;
                op[(size_t)(4 * j + 3) * HW] = v.w;
            }
        }
    }
}

// ---------------- fallback: exact fp32 full scan, warp per token -----------
__global__ void __launch_bounds__(256, 1)
vq_fb(const float* __restrict__ input, const float* __restrict__ cb,
      float* __restrict__ out) {
    const int n = g_nfb;
    const int gw   = (blockIdx.x * 256 + threadIdx.x) >> 5;   // 1024 warps
    const int lane = threadIdx.x & 31;

    for (int t = gw; t < n; t += 1024) {
        const int row = g_fb[t];
        const int b   = row >> 12;
        const int hw  = row & (HW - 1);
        const float* xp = input + (size_t)b * D * HW + hw;

        float xa = xp[(size_t)lane * HW];
        float xb = xp[(size_t)(lane + 32) * HW];
        float xr[64];
        #pragma unroll
        for (int k = 0; k < 64; ++k)
            xr[k] = __shfl_sync(0xffffffffu, (k < 32) ? xa : xb, k & 31);
        float ssx = 0.0f;
        #pragma unroll
        for (int k = 0; k < 64; ++k) ssx = fmaf(xr[k], xr[k], ssx);

        float bd = 3.4e38f;
        int   bi = 0;
        #pragma unroll 1
        for (int j = 0; j < 32; ++j) {
            const int c = lane + 32 * j;    // ascending per lane
            const float* e = cb + c * D;
            float dot = 0.0f;
            #pragma unroll
            for (int k = 0; k < 64; ++k)
                dot = fmaf(xr[k], __ldg(e + k), dot);
            float dist = (ssx + __ldg(&g_sse[c])) - 2.0f * dot;
            if (dist < bd) { bd = dist; bi = c; }
        }
        #pragma unroll
        for (int off = 16; off >= 1; off >>= 1) {
            float od = __shfl_xor_sync(0xffffffffu, bd, off);
            int   oi = __shfl_xor_sync(0xffffffffu, bi, off);
            if (od < bd || (od == bd && oi < bi)) { bd = od; bi = oi; }
        }
        float* op = out + (size_t)b * D * HW + hw;
        #pragma unroll
        for (int k = lane; k < 64; k += 32)
            op[(size_t)k * HW] = __ldg(cb + bi * D + k);
    }
}

extern "C" void kernel_launch(void* const* d_in, const int* in_sizes, int n_in,
                              void* d_out, int out_size) {
    const float* input    = (const float*)d_in[0];   // [16, 64, 64, 64] fp32 NCHW
    const float* codebook = (const float*)d_in[1];   // [1024, 64] fp32
    float*       out      = (float*)d_out;

    cudaFuncSetAttribute(vq_main, cudaFuncAttributeMaxDynamicSharedMemorySize, SMEM_REQ);
    vq_prep<<<64, 1024>>>(codebook);
    vq_main<<<128, THREADS, SMEM_REQ>>>(input, codebook, out);
    vq_fb<<<128, 256>>>(input, codebook, out);
}

// round 15
// speedup vs baseline: 1.0991x; 1.0991x over previous
#include <cuda_runtime.h>
#include <cuda_fp16.h>
#include <cstdint>

#define D       64
#define HW      4096
#define KCODES  1024
#define NTOK    65536

#define ESCALE    1024.0f
#define NEG2EINV (-0.001953125f)     // -2/1024 : d' = 64 + sse - 2*dot
#define BITS60    0x42700000u        // bits(60.0f), subtracted base

// ---------------- device scratch (no allocation allowed) -------------------
__device__ uint4 g_Eh4[8192];     // 128KB: hi-plane B fragments, all 1024 codes
__device__ float g_sse[KCODES];
__device__ int   g_nfb;           // fallback count
__device__ int   g_fb[NTOK];      // fallback token list

__device__ __forceinline__ uint32_t packh(float x0, float x1) {
    uint32_t r;
    asm("cvt.rn.f16x2.f32 %0, %1, %2;" : "=r"(r) : "f"(x1), "f"(x0));
    return r;
}

// C += A(f16 16x16) * B(f16 16x8), fp32 accumulate.
__device__ __forceinline__ void mma_f16(float c[4], const uint32_t* a,
                                        uint32_t b0, uint32_t b1) {
    asm("mma.sync.aligned.m16n8k16.row.col.f32.f16.f16.f32 "
        "{%0,%1,%2,%3}, {%4,%5,%6,%7}, {%8,%9}, {%0,%1,%2,%3};"
        : "+f"(c[0]), "+f"(c[1]), "+f"(c[2]), "+f"(c[3])
        : "r"(a[0]), "r"(a[1]), "r"(a[2]), "r"(a[3]), "r"(b0), "r"(b1));
}

// ---------------- prep: codebook -> f16 hi B-fragments (scaled) + sse ------
__global__ void vq_prep(const float* __restrict__ cb) {
    int id = blockIdx.x * blockDim.x + threadIdx.x;   // 65536 = 1024*64
    if (id == 0) g_nfb = 0;
    int n = id >> 6, k = id & 63;
    __half hi = __float2half(cb[id] * ESCALE);
    int ntile = n >> 3, nrow = n & 7;
    int kstep = k >> 4, kin = k & 15;
    int j    = kin >> 3;
    int cb4  = (kin & 7) >> 1;
    int elem = k & 1;
    int idx2 = (ntile * 4 + kstep) * 32 + nrow * 4 + cb4;   // uint2 slots
    ((__half*)g_Eh4)[idx2 * 4 + j * 2 + elem] = hi;
    if (k == 0) {   // sequential row sum, unscaled
        const float* r = cb + n * D;
        float s = 0.0f;
        for (int d0 = 0; d0 < D; ++d0) s += r[d0] * r[d0];
        g_sse[n] = s;
    }
}

#define SMEM_REQ (131072 + 8192)
#define THREADS  512

// branchless sorted top-3 insert of packed key v into (m1 <= m2 <= m3)
#define INS3(m1, m2, m3, v)                       \
    {                                             \
        uint32_t _t = max(m1, v);                 \
        m1 = min(m1, v);                          \
        uint32_t _t2 = max(m2, _t);               \
        m2 = min(m2, _t);                         \
        m3 = min(m3, _t2);                        \
    }

// ---------------- main: hi-plane screening + uniform top-2 refine ----------
__global__ void __launch_bounds__(THREADS, 1)
vq_main(const float* __restrict__ input, const float* __restrict__ cb,
        float* __restrict__ out) {
    extern __shared__ char smraw[];
    uint2* sB2  = (uint2*)smraw;                 // 16384 uint2 = 128KB
    float* sSse = (float*)(smraw + 131072);      // exact sse, 1024 floats
    float* sSsp = (float*)(smraw + 135168);      // 64 + sse,  1024 floats

    const int tid  = threadIdx.x;
    const int w    = tid >> 5;
    const int lane = tid & 31;
    const int grp  = lane >> 2;
    const int cb4  = lane & 3;

    // stage ALL 1024 codes' hi fragments + sse (+64-biased copy) once
    {
        uint4* d4 = (uint4*)smraw;
        #pragma unroll
        for (int i = 0; i < 16; ++i)
            d4[tid + i * THREADS] = g_Eh4[tid + i * THREADS];
        #pragma unroll
        for (int i = 0; i < 2; ++i) {
            float s = g_sse[tid + i * THREADS];
            sSse[tid + i * THREADS] = s;
            sSsp[tid + i * THREADS] = 64.0f + s;
        }
    }
    __syncthreads();

    #pragma unroll 1
    for (int p = 0; p < 2; ++p) {
        const int base = blockIdx.x * 512 + p * 256 + w * 16;

        // ---- A hi fragment: 16 tokens ----
        uint32_t Ahi[16];
        float ssx0, ssx1;
        {
            const int row0 = base + grp;
            const int b    = row0 >> 12;
            const int hw   = row0 & (HW - 1);
            const float* p0 = input + (size_t)b * D * HW + hw;
            const float* p1 = p0 + 8;
            float s0 = 0.0f, s1 = 0.0f;
            #pragma unroll
            for (int ks = 0; ks < 4; ++ks) {
                const int k0 = ks * 16 + 2 * cb4;
                float xa, xb;
                xa = p0[(size_t)k0 * HW];        xb = p0[(size_t)(k0 + 1) * HW];
                s0 = fmaf(xa, xa, s0);           s0 = fmaf(xb, xb, s0);
                Ahi[ks * 4 + 0] = packh(xa, xb);
                xa = p1[(size_t)k0 * HW];        xb = p1[(size_t)(k0 + 1) * HW];
                s1 = fmaf(xa, xa, s1);           s1 = fmaf(xb, xb, s1);
                Ahi[ks * 4 + 1] = packh(xa, xb);
                xa = p0[(size_t)(k0 + 8) * HW];  xb = p0[(size_t)(k0 + 9) * HW];
                s0 = fmaf(xa, xa, s0);           s0 = fmaf(xb, xb, s0);
                Ahi[ks * 4 + 2] = packh(xa, xb);
                xa = p1[(size_t)(k0 + 8) * HW];  xb = p1[(size_t)(k0 + 9) * HW];
                s1 = fmaf(xa, xa, s1);           s1 = fmaf(xb, xb, s1);
                Ahi[ks * 4 + 3] = packh(xa, xb);
            }
            s0 += __shfl_xor_sync(0xffffffffu, s0, 1);
            s0 += __shfl_xor_sync(0xffffffffu, s0, 2);
            s1 += __shfl_xor_sync(0xffffffffu, s1, 1);
            s1 += __shfl_xor_sync(0xffffffffu, s1, 2);
            ssx0 = s0;
            ssx1 = s1;
        }

        // packed top-3 per token (u = (bits(d')-bits(60))*1024 | kg)
        uint32_t m1[2] = {0xFFFFFFFFu, 0xFFFFFFFFu};
        uint32_t m2[2] = {0xFFFFFFFFu, 0xFFFFFFFFu};
        uint32_t m3[2] = {0xFFFFFFFFu, 0xFFFFFFFFu};

        // ---- screening: hi*hi only, all 1024 codes, branchless epilogue ----
        #pragma unroll 2
        for (int nt = 0; nt < 128; ++nt) {
            float C[4] = {0.0f, 0.0f, 0.0f, 0.0f};
            #pragma unroll
            for (int ks = 0; ks < 4; ++ks) {
                uint2 B = sB2[(nt * 4 + ks) * 32 + lane];
                mma_f16(C, &Ahi[ks * 4], B.x, B.y);
            }
            const int kg = nt * 8 + 2 * cb4;
            float2 sp = *(const float2*)&sSsp[kg];
            float d00 = fmaf(C[0], NEG2EINV, sp.x);
            float d01 = fmaf(C[1], NEG2EINV, sp.y);
            float d10 = fmaf(C[2], NEG2EINV, sp.x);
            float d11 = fmaf(C[3], NEG2EINV, sp.y);
            uint32_t u00 = (__float_as_uint(d00) - BITS60) * 1024u + (uint32_t)kg;
            uint32_t u01 = (__float_as_uint(d01) - BITS60) * 1024u + (uint32_t)(kg + 1);
            uint32_t u10 = (__float_as_uint(d10) - BITS60) * 1024u + (uint32_t)kg;
            uint32_t u11 = (__float_as_uint(d11) - BITS60) * 1024u + (uint32_t)(kg + 1);
            INS3(m1[0], m2[0], m3[0], u00);
            INS3(m1[0], m2[0], m3[0], u01);
            INS3(m1[1], m2[1], m3[1], u10);
            INS3(m1[1], m2[1], m3[1], u11);
        }

        // ---- merge top-3 across the 4 cb4 lanes (packed => lex-correct) ----
        #pragma unroll
        for (int off = 1; off <= 2; off <<= 1) {
            #pragma unroll
            for (int h = 0; h < 2; ++h) {
                uint32_t o1 = __shfl_xor_sync(0xffffffffu, m1[h], off);
                uint32_t o2 = __shfl_xor_sync(0xffffffffu, m2[h], off);
                uint32_t o3 = __shfl_xor_sync(0xffffffffu, m3[h], off);
                INS3(m1[h], m2[h], m3[h], o1);
                INS3(m1[h], m2[h], m3[h], o2);
                INS3(m1[h], m2[h], m3[h], o3);
            }
        }

        // ---- uniform exact top-2 refinement + tier-3 flag + output ----
        if (cb4 < 2) {
            const int h    = cb4;
            const int row  = base + grp + h * 8;
            const int b    = row >> 12;
            const int hw   = row & (HW - 1);
            const float ssx = h ? ssx1 : ssx0;

            const int i1 = (int)(m1[h] & 1023u);
            const int i2 = (int)(m2[h] & 1023u);

            // exact fp32 refine of {i1, i2}; ssx common-mode within the pair
            const float* xr = input + (size_t)b * D * HW + hw;
            const float4* e1 = (const float4*)(cb + i1 * D);
            const float4* e2 = (const float4*)(cb + i2 * D);
            float dot1 = 0.0f, dot2 = 0.0f;
            #pragma unroll
            for (int j = 0; j < 16; ++j) {
                float4 a = __ldg(e1 + j);
                float4 c = __ldg(e2 + j);
                float x0 = xr[(size_t)(4 * j + 0) * HW];
                float x1 = xr[(size_t)(4 * j + 1) * HW];
                float x2 = xr[(size_t)(4 * j + 2) * HW];
                float x3 = xr[(size_t)(4 * j + 3) * HW];
                dot1 = fmaf(x0, a.x, dot1); dot1 = fmaf(x1, a.y, dot1);
                dot1 = fmaf(x2, a.z, dot1); dot1 = fmaf(x3, a.w, dot1);
                dot2 = fmaf(x0, c.x, dot2); dot2 = fmaf(x1, c.y, dot2);
                dot2 = fmaf(x2, c.z, dot2); dot2 = fmaf(x3, c.w, dot2);
            }
            float r1 = (ssx + sSse[i1]) - 2.0f * dot1;
            float r2 = (ssx + sSse[i2]) - 2.0f * dot2;
            int win = i1;
            if (r2 < r1 || (r2 == r1 && i2 < i1)) win = i2;

            // tier-3: a 3rd code within the rigorous screening error bound
            float dscr1 = __uint_as_float((m1[h] >> 10) + BITS60);
            float dscr3 = __uint_as_float((m3[h] >> 10) + BITS60);
            float T = fmaf(sqrtf(ssx), 3.1e-5f, 5.0e-5f);
            if (dscr3 - dscr1 < T) {
                int slot = atomicAdd(&g_nfb, 1);
                g_fb[slot] = row;
            }

            const float4* e  = (const float4*)cb + win * (D / 4);
            float*        op = out + (size_t)b * D * HW + hw;
            #pragma unroll
            for (int j = 0; j < D / 4; ++j) {
                float4 v = __ldg(e + j);
                op[(size_t)(4 * j + 0) * HW] = v.x;
                op[(size_t)(4 * j + 1) * HW] = v.y;
                op[(size_t)(4 * j + 2) * HW] = v.z;
                op[(size_t)(4 * j + 3) * HW] = v.w;
            }
        }
    }
}

// ---------------- fallback: exact fp32 full scan, warp per token -----------
__global__ void __launch_bounds__(256, 1)
vq_fb(const float* __restrict__ input, const float* __restrict__ cb,
      float* __restrict__ out) {
    const int n = g_nfb;
    const int gw   = (blockIdx.x * 256 + threadIdx.x) >> 5;   // 1024 warps
    const int lane = threadIdx.x & 31;

    for (int t = gw; t < n; t += 1024) {
        const int row = g_fb[t];
        const int b   = row >> 12;
        const int hw  = row & (HW - 1);
        const float* xp = input + (size_t)b * D * HW + hw;

        float xa = xp[(size_t)lane * HW];
        float xb = xp[(size_t)(lane + 32) * HW];
        float xr[64];
        #pragma unroll
        for (int k = 0; k < 64; ++k)
            xr[k] = __shfl_sync(0xffffffffu, (k < 32) ? xa : xb, k & 31);
        float ssx = 0.0f;
        #pragma unroll
        for (int k = 0; k < 64; ++k) ssx = fmaf(xr[k], xr[k], ssx);

        float bd = 3.4e38f;
        int   bi = 0;
        #pragma unroll 1
        for (int j = 0; j < 32; ++j) {
            const int c = lane + 32 * j;    // ascending per lane
            const float* e = cb + c * D;
            float dot = 0.0f;
            #pragma unroll
            for (int k = 0; k < 64; ++k)
                dot = fmaf(xr[k], __ldg(e + k), dot);
            float dist = (ssx + __ldg(&g_sse[c])) - 2.0f * dot;
            if (dist < bd) { bd = dist; bi = c; }
        }
        #pragma unroll
        for (int off = 16; off >= 1; off >>= 1) {
            float od = __shfl_xor_sync(0xffffffffu, bd, off);
            int   oi = __shfl_xor_sync(0xffffffffu, bi, off);
            if (od < bd || (od == bd && oi < bi)) { bd = od; bi = oi; }
        }
        float* op = out + (size_t)b * D * HW + hw;
        #pragma unroll
        for (int k = lane; k < 64; k += 32)
            op[(size_t)k * HW] = __ldg(cb + bi * D + k);
    }
}

extern "C" void kernel_launch(void* const* d_in, const int* in_sizes, int n_in,
                              void* d_out, int out_size) {
    const float* input    = (const float*)d_in[0];   // [16, 64, 64, 64] fp32 NCHW
    const float* codebook = (const float*)d_in[1];   // [1024, 64] fp32
    float*       out      = (float*)d_out;

    cudaFuncSetAttribute(vq_main, cudaFuncAttributeMaxDynamicSharedMemorySize, SMEM_REQ);
    vq_prep<<<64, 1024>>>(codebook);
    vq_main<<<128, THREADS, SMEM_REQ>>>(input, codebook, out);
    vq_fb<<<128, 256>>>(input, codebook, out);
}

// round 16
// speedup vs baseline: 3.8694x; 3.5204x over previous
#include <cuda_runtime.h>
#include <cuda_fp16.h>
#include <cstdint>

#define D       64
#define HW      4096
#define KCODES  1024
#define NTOK    65536

#define ESCALE    1024.0f
#define NEG2EINV (-0.001953125f)     // -2/1024 : d' = 64 + sse - 2*dot
#define BITS60    0x42700000u        // bits(60.0f), key bias

// ---------------- device scratch (no allocation allowed) -------------------
__device__ uint4 g_Eh4[8192];        // 128KB: hi-plane B fragments, all 1024 codes
__device__ float g_sse[KCODES];
__device__ float g_cbT[D * KCODES];  // 256KB: transposed codebook [k][n]
__device__ int   g_nfb;              // fallback count
__device__ int   g_fb[NTOK];         // fallback token list

__device__ __forceinline__ uint32_t packh(float x0, float x1) {
    uint32_t r;
    asm("cvt.rn.f16x2.f32 %0, %1, %2;" : "=r"(r) : "f"(x1), "f"(x0));
    return r;
}

// C += A(f16 16x16) * B(f16 16x8), fp32 accumulate.
__device__ __forceinline__ void mma_f16(float c[4], const uint32_t* a,
                                        uint32_t b0, uint32_t b1) {
    asm("mma.sync.aligned.m16n8k16.row.col.f32.f16.f16.f32 "
        "{%0,%1,%2,%3}, {%4,%5,%6,%7}, {%8,%9}, {%0,%1,%2,%3};"
        : "+f"(c[0]), "+f"(c[1]), "+f"(c[2]), "+f"(c[3])
        : "r"(a[0]), "r"(a[1]), "r"(a[2]), "r"(a[3]), "r"(b0), "r"(b1));
}

// ---------------- prep: fragments + sse + transposed codebook --------------
__global__ void vq_prep(const float* __restrict__ cb) {
    int id = blockIdx.x * blockDim.x + threadIdx.x;   // 65536 = 1024*64
    if (id == 0) g_nfb = 0;
    int n = id >> 6, k = id & 63;
    float e = cb[id];
    g_cbT[k * KCODES + n] = e;                  // transpose for fallback
    __half hi = __float2half(e * ESCALE);
    int ntile = n >> 3, nrow = n & 7;
    int kstep = k >> 4, kin = k & 15;
    int j    = kin >> 3;
    int cb4  = (kin & 7) >> 1;
    int elem = k & 1;
    int idx2 = (ntile * 4 + kstep) * 32 + nrow * 4 + cb4;   // uint2 slots
    ((__half*)g_Eh4)[idx2 * 4 + j * 2 + elem] = hi;
    if (k == 0) {   // sequential row sum, unscaled
        const float* r = cb + n * D;
        float s = 0.0f;
        for (int d0 = 0; d0 < D; ++d0) s += r[d0] * r[d0];
        g_sse[n] = s;
    }
}

#define SMEM_REQ (131072 + 8192)
#define THREADS  512

// branchless sorted top-3 insert of packed key v into (m1 <= m2 <= m3)
#define INS3(m1, m2, m3, v)                       \
    {                                             \
        uint32_t _t = max(m1, v);                 \
        m1 = min(m1, v);                          \
        uint32_t _t2 = max(m2, _t);               \
        m2 = min(m2, _t);                         \
        m3 = min(m3, _t2);                        \
    }

// ---------------- main: hi-plane screening + uniform top-2 refine ----------
__global__ void __launch_bounds__(THREADS, 1)
vq_main(const float* __restrict__ input, const float* __restrict__ cb,
        float* __restrict__ out) {
    extern __shared__ char smraw[];
    uint2* sB2  = (uint2*)smraw;                 // 16384 uint2 = 128KB
    float* sSse = (float*)(smraw + 131072);      // exact sse, 1024 floats
    float* sSsp = (float*)(smraw + 135168);      // 64 + sse,  1024 floats

    const int tid  = threadIdx.x;
    const int w    = tid >> 5;
    const int lane = tid & 31;
    const int grp  = lane >> 2;
    const int cb4  = lane & 3;

    // stage ALL 1024 codes' hi fragments + sse (+64-biased copy) once
    {
        uint4* d4 = (uint4*)smraw;
        #pragma unroll
        for (int i = 0; i < 16; ++i)
            d4[tid + i * THREADS] = g_Eh4[tid + i * THREADS];
        #pragma unroll
        for (int i = 0; i < 2; ++i) {
            float s = g_sse[tid + i * THREADS];
            sSse[tid + i * THREADS] = s;
            sSsp[tid + i * THREADS] = 64.0f + s;
        }
    }
    __syncthreads();

    #pragma unroll 1
    for (int p = 0; p < 2; ++p) {
        const int base = blockIdx.x * 512 + p * 256 + w * 16;

        // ---- A hi fragment: 16 tokens ----
        uint32_t Ahi[16];
        float ssx0, ssx1;
        {
            const int row0 = base + grp;
            const int b    = row0 >> 12;
            const int hw   = row0 & (HW - 1);
            const float* p0 = input + (size_t)b * D * HW + hw;
            const float* p1 = p0 + 8;
            float s0 = 0.0f, s1 = 0.0f;
            #pragma unroll
            for (int ks = 0; ks < 4; ++ks) {
                const int k0 = ks * 16 + 2 * cb4;
                float xa, xb;
                xa = p0[(size_t)k0 * HW];        xb = p0[(size_t)(k0 + 1) * HW];
                s0 = fmaf(xa, xa, s0);           s0 = fmaf(xb, xb, s0);
                Ahi[ks * 4 + 0] = packh(xa, xb);
                xa = p1[(size_t)k0 * HW];        xb = p1[(size_t)(k0 + 1) * HW];
                s1 = fmaf(xa, xa, s1);           s1 = fmaf(xb, xb, s1);
                Ahi[ks * 4 + 1] = packh(xa, xb);
                xa = p0[(size_t)(k0 + 8) * HW];  xb = p0[(size_t)(k0 + 9) * HW];
                s0 = fmaf(xa, xa, s0);           s0 = fmaf(xb, xb, s0);
                Ahi[ks * 4 + 2] = packh(xa, xb);
                xa = p1[(size_t)(k0 + 8) * HW];  xb = p1[(size_t)(k0 + 9) * HW];
                s1 = fmaf(xa, xa, s1);           s1 = fmaf(xb, xb, s1);
                Ahi[ks * 4 + 3] = packh(xa, xb);
            }
            s0 += __shfl_xor_sync(0xffffffffu, s0, 1);
            s0 += __shfl_xor_sync(0xffffffffu, s0, 2);
            s1 += __shfl_xor_sync(0xffffffffu, s1, 1);
            s1 += __shfl_xor_sync(0xffffffffu, s1, 2);
            ssx0 = s0;
            ssx1 = s1;
        }

        // packed top-3 per token: key = bits(d')*1024 + (kg - BITS60*1024)
        // (wrap-exact: 60 < d' < 88 so bits(d')-BITS60 < 2^22, key < 2^32)
        uint32_t m1[2] = {0xFFFFFFFFu, 0xFFFFFFFFu};
        uint32_t m2[2] = {0xFFFFFFFFu, 0xFFFFFFFFu};
        uint32_t m3[2] = {0xFFFFFFFFu, 0xFFFFFFFFu};
        const uint32_t KBIAS = 0u - BITS60 * 1024u;

        // ---- screening: hi*hi only, all 1024 codes, branchless epilogue ----
        #pragma unroll 4
        for (int nt = 0; nt < 128; ++nt) {
            float C[4] = {0.0f, 0.0f, 0.0f, 0.0f};
            #pragma unroll
            for (int ks = 0; ks < 4; ++ks) {
                uint2 B = sB2[(nt * 4 + ks) * 32 + lane];
                mma_f16(C, &Ahi[ks * 4], B.x, B.y);
            }
            const int kg = nt * 8 + 2 * cb4;
            float2 sp = *(const float2*)&sSsp[kg];
            float d00 = fmaf(C[0], NEG2EINV, sp.x);
            float d01 = fmaf(C[1], NEG2EINV, sp.y);
            float d10 = fmaf(C[2], NEG2EINV, sp.x);
            float d11 = fmaf(C[3], NEG2EINV, sp.y);
            const uint32_t kb = KBIAS + (uint32_t)kg;
            uint32_t u00 = __float_as_uint(d00) * 1024u + kb;
            uint32_t u01 = __float_as_uint(d01) * 1024u + kb + 1u;
            uint32_t u10 = __float_as_uint(d10) * 1024u + kb;
            uint32_t u11 = __float_as_uint(d11) * 1024u + kb + 1u;
            INS3(m1[0], m2[0], m3[0], u00);
            INS3(m1[0], m2[0], m3[0], u01);
            INS3(m1[1], m2[1], m3[1], u10);
            INS3(m1[1], m2[1], m3[1], u11);
        }

        // ---- merge top-3 across the 4 cb4 lanes (packed => lex-correct) ----
        #pragma unroll
        for (int off = 1; off <= 2; off <<= 1) {
            #pragma unroll
            for (int h = 0; h < 2; ++h) {
                uint32_t o1 = __shfl_xor_sync(0xffffffffu, m1[h], off);
                uint32_t o2 = __shfl_xor_sync(0xffffffffu, m2[h], off);
                uint32_t o3 = __shfl_xor_sync(0xffffffffu, m3[h], off);
                INS3(m1[h], m2[h], m3[h], o1);
                INS3(m1[h], m2[h], m3[h], o2);
                INS3(m1[h], m2[h], m3[h], o3);
            }
        }

        // ---- uniform exact top-2 refinement + tier-3 flag + output ----
        if (cb4 < 2) {
            const int h    = cb4;
            const int row  = base + grp + h * 8;
            const int b    = row >> 12;
            const int hw   = row & (HW - 1);
            const float ssx = h ? ssx1 : ssx0;

            const int i1 = (int)(m1[h] & 1023u);
            const int i2 = (int)(m2[h] & 1023u);

            // exact fp32 refine of {i1, i2}; ssx common-mode within the pair
            const float* xr = input + (size_t)b * D * HW + hw;
            const float4* e1 = (const float4*)(cb + i1 * D);
            const float4* e2 = (const float4*)(cb + i2 * D);
            float dot1 = 0.0f, dot2 = 0.0f;
            #pragma unroll
            for (int j = 0; j < 16; ++j) {
                float4 a = __ldg(e1 + j);
                float4 c = __ldg(e2 + j);
                float x0 = xr[(size_t)(4 * j + 0) * HW];
                float x1 = xr[(size_t)(4 * j + 1) * HW];
                float x2 = xr[(size_t)(4 * j + 2) * HW];
                float x3 = xr[(size_t)(4 * j + 3) * HW];
                dot1 = fmaf(x0, a.x, dot1); dot1 = fmaf(x1, a.y, dot1);
                dot1 = fmaf(x2, a.z, dot1); dot1 = fmaf(x3, a.w, dot1);
                dot2 = fmaf(x0, c.x, dot2); dot2 = fmaf(x1, c.y, dot2);
                dot2 = fmaf(x2, c.z, dot2); dot2 = fmaf(x3, c.w, dot2);
            }
            float r1 = (ssx + sSse[i1]) - 2.0f * dot1;
            float r2 = (ssx + sSse[i2]) - 2.0f * dot2;
            int win = i1;
            if (r2 < r1 || (r2 == r1 && i2 < i1)) win = i2;

            // tier-3: a 3rd code within the rigorous screening error bound
            float dscr1 = __uint_as_float((m1[h] >> 10) + BITS60);
            float dscr3 = __uint_as_float((m3[h] >> 10) + BITS60);
            float T = fmaf(sqrtf(ssx), 3.1e-5f, 5.0e-5f);
            if (dscr3 - dscr1 < T) {
                int slot = atomicAdd(&g_nfb, 1);
                g_fb[slot] = row;
            }

            const float4* e  = (const float4*)cb + win * (D / 4);
            float*        op = out + (size_t)b * D * HW + hw;
            #pragma unroll
            for (int j = 0; j < D / 4; ++j) {
                float4 v = __ldg(e + j);
                op[(size_t)(4 * j + 0) * HW] = v.x;
                op[(size_t)(4 * j + 1) * HW] = v.y;
                op[(size_t)(4 * j + 2) * HW] = v.z;
                op[(size_t)(4 * j + 3) * HW] = v.w;
            }
        }
    }
}

// ------- fallback: exact fp32 full scan, warp/token, coalesced via g_cbT ---
__global__ void __launch_bounds__(256, 1)
vq_fb(const float* __restrict__ input, const float* __restrict__ cb,
      float* __restrict__ out) {
    const int n = g_nfb;
    const int gw   = (blockIdx.x * 256 + threadIdx.x) >> 5;   // 1024 warps
    const int lane = threadIdx.x & 31;

    for (int t = gw; t < n; t += 1024) {
        const int row = g_fb[t];
        const int b   = row >> 12;
        const int hw  = row & (HW - 1);
        const float* xp = input + (size_t)b * D * HW + hw;

        float xa = xp[(size_t)lane * HW];
        float xb = xp[(size_t)(lane + 32) * HW];
        float xr[64];
        #pragma unroll
        for (int k = 0; k < 64; ++k)
            xr[k] = __shfl_sync(0xffffffffu, (k < 32) ? xa : xb, k & 31);
        float ssx = 0.0f;
        #pragma unroll
        for (int k = 0; k < 64; ++k) ssx = fmaf(xr[k], xr[k], ssx);

        float bd = 3.4e38f;
        int   bi = 0;
        #pragma unroll 1
        for (int j = 0; j < 32; ++j) {
            const int c = lane + 32 * j;    // ascending per lane
            float dot = 0.0f;
            #pragma unroll
            for (int k = 0; k < 64; ++k)    // coalesced: lanes read consecutive n
                dot = fmaf(xr[k], __ldg(&g_cbT[k * KCODES + c]), dot);
            float dist = (ssx + __ldg(&g_sse[c])) - 2.0f * dot;
            if (dist < bd) { bd = dist; bi = c; }
        }
        #pragma unroll
        for (int off = 16; off >= 1; off >>= 1) {
            float od = __shfl_xor_sync(0xffffffffu, bd, off);
            int   oi = __shfl_xor_sync(0xffffffffu, bi, off);
            if (od < bd || (od == bd && oi < bi)) { bd = od; bi = oi; }
        }
        float* op = out + (size_t)b * D * HW + hw;
        #pragma unroll
        for (int k = lane; k < 64; k += 32)
            op[(size_t)k * HW] = __ldg(cb + bi * D + k);
    }
}

extern "C" void kernel_launch(void* const* d_in, const int* in_sizes, int n_in,
                              void* d_out, int out_size) {
    const float* input    = (const float*)d_in[0];   // [16, 64, 64, 64] fp32 NCHW
    const float* codebook = (const float*)d_in[1];   // [1024, 64] fp32
    float*       out      = (float*)d_out;

    cudaFuncSetAttribute(vq_main, cudaFuncAttributeMaxDynamicSharedMemorySize, SMEM_REQ);
    vq_prep<<<64, 1024>>>(codebook);
    vq_main<<<128, THREADS, SMEM_REQ>>>(input, codebook, out);
    vq_fb<<<128, 256>>>(input, codebook, out);
}